// round 9
// baseline (speedup 1.0000x reference)
#include <cuda_runtime.h>
#include <cuda_bf16.h>
#include <cstdint>

// ---------------------------------------------------------------------------
// FMoELinearProj via legacy HMMA (mma.sync.m16n8k16.bf16).
// fp32 emulated as bf16 2-term split: hi*hi + hi*lo + lo*hi (3 MMAs).
// R8: smem-bandwidth fix — 64x64 warp tiles (85 B/HMMA vs 128), CTA 128x256,
// 8 warps, 2-stage smem. A prefetched (regs or cp.async), B split post-MMA.
// GEMM1 emits y pre-split bf16; GEMM2 consumes it via cp.async.
// ---------------------------------------------------------------------------

#define BM 128
#define BN 256
#define NTH 256
#define SROW 80                         // padded smem row: 64B data + 16B pad
#define ATILE 10240                     // 128 rows * SROW
#define BTILE 20480                     // 256 rows * SROW
#define OFF_ALO ATILE
#define OFF_BHI (2 * ATILE)
#define OFF_BLO (2 * ATILE + BTILE)
#define STAGEB (2 * ATILE + 2 * BTILE)  // 61440
#define BIAS_OFF (2 * STAGEB)           // 122880
#define SMEM_TOTAL (BIAS_OFF + 1024)

__device__ int  g_off[65];
__device__ int2 g_tiles[1024];
__device__ int  g_ntiles;
__device__ __nv_bfloat16 g_yhi[8192ull * 4096];
__device__ __nv_bfloat16 g_ylo[8192ull * 4096];

// ------------------------------- helpers -----------------------------------
__device__ __forceinline__ uint32_t smem_u32(const void* p) {
    uint32_t a;
    asm("{ .reg .u64 t; cvta.to.shared.u64 t, %1; cvt.u32.u64 %0, t; }"
        : "=r"(a) : "l"(p));
    return a;
}
__device__ __forceinline__ void ldsm4(uint32_t* r, uint32_t addr) {
    asm volatile("ldmatrix.sync.aligned.m8n8.x4.shared.b16 {%0,%1,%2,%3}, [%4];"
                 : "=r"(r[0]), "=r"(r[1]), "=r"(r[2]), "=r"(r[3]) : "r"(addr));
}
__device__ __forceinline__ void mma16816(float* c, const uint32_t* a,
                                         const uint32_t* b) {
    asm volatile(
        "mma.sync.aligned.m16n8k16.row.col.f32.bf16.bf16.f32 "
        "{%0,%1,%2,%3}, {%4,%5,%6,%7}, {%8,%9}, {%0,%1,%2,%3};"
        : "+f"(c[0]), "+f"(c[1]), "+f"(c[2]), "+f"(c[3])
        : "r"(a[0]), "r"(a[1]), "r"(a[2]), "r"(a[3]), "r"(b[0]), "r"(b[1]));
}
__device__ __forceinline__ void cpa16(uint32_t dst, const void* src,
                                      uint32_t ssize) {
    asm volatile("cp.async.cg.shared.global [%0], [%1], 16, %2;"
                 :: "r"(dst), "l"(src), "r"(ssize) : "memory");
}
#define CP_COMMIT() asm volatile("cp.async.commit_group;" ::: "memory")
#define CP_WAIT0()  asm volatile("cp.async.wait_group 0;" ::: "memory")

__device__ __forceinline__ void sts128(uint32_t a, uint32_t r0, uint32_t r1,
                                       uint32_t r2, uint32_t r3) {
    asm volatile("st.shared.v4.b32 [%0], {%1, %2, %3, %4};"
                 :: "r"(a), "r"(r0), "r"(r1), "r"(r2), "r"(r3) : "memory");
}
__device__ __forceinline__ float trunc16f(float a) {
    return __uint_as_float(__float_as_uint(a) & 0xFFFF0000u);
}
__device__ __forceinline__ uint32_t prmt_hi(float a, float b) {
    uint32_t d;
    asm("prmt.b32 %0, %1, %2, 0x7632;" : "=r"(d)
        : "r"(__float_as_uint(a)), "r"(__float_as_uint(b)));
    return d;
}
__device__ __forceinline__ uint32_t pack_lo(float e0, float e1) {
    uint32_t d;
    asm("cvt.rn.bf16x2.f32 %0, %1, %2;" : "=r"(d) : "f"(e1), "f"(e0));
    return d;
}
// Split 8 consecutive fp32 (2 float4) into 16B bf16 hi + 16B bf16 lo, store.
__device__ __forceinline__ void split_sts(uint32_t hib, uint32_t lob,
                                          float4 u0, float4 u1) {
    uint32_t h0 = prmt_hi(u0.x, u0.y);
    uint32_t h1 = prmt_hi(u0.z, u0.w);
    uint32_t h2 = prmt_hi(u1.x, u1.y);
    uint32_t h3 = prmt_hi(u1.z, u1.w);
    uint32_t l0 = pack_lo(u0.x - trunc16f(u0.x), u0.y - trunc16f(u0.y));
    uint32_t l1 = pack_lo(u0.z - trunc16f(u0.z), u0.w - trunc16f(u0.w));
    uint32_t l2 = pack_lo(u1.x - trunc16f(u1.x), u1.y - trunc16f(u1.y));
    uint32_t l3 = pack_lo(u1.z - trunc16f(u1.z), u1.w - trunc16f(u1.w));
    sts128(hib, h0, h1, h2, h3);
    sts128(lob, l0, l1, l2, l3);
}

// ------------------------------ setup kernel -------------------------------
__global__ void setup_kernel(const int* __restrict__ counts, int E) {
    if (threadIdx.x == 0 && blockIdx.x == 0) {
        int off = 0, nt = 0;
        for (int e = 0; e < E; ++e) {
            g_off[e] = off;
            int c = counts[e];
            for (int m = 0; m < c; m += BM) { g_tiles[nt].x = e; g_tiles[nt].y = m; ++nt; }
            off += c;
        }
        g_off[E] = off;
        g_ntiles = nt;
    }
}

// ------------------------------ main GEMM kernel ---------------------------
// C[row, n] = sum_k A[row, k] * B[e, n, k] (+ bias).
// A_BF16: A pre-split (g_yhi/g_ylo), fetched via cp.async. SPLIT_OUT: C -> y split.
template <bool ADD_BIAS, bool A_BF16, bool SPLIT_OUT>
__global__ __launch_bounds__(NTH, 1)
void moe_hmma(const float* __restrict__ Af,
              const __nv_bfloat16* __restrict__ Ahi,
              const __nv_bfloat16* __restrict__ Alo,
              const float* __restrict__ Bf,
              const float* __restrict__ bias, float* __restrict__ Cf,
              int K, int N)
{
    const int tile = blockIdx.y;
    if (tile >= g_ntiles) return;
    const int e    = g_tiles[tile].x;
    const int m0   = g_tiles[tile].y;
    const int row0 = g_off[e] + m0;
    int mrows = g_off[e + 1] - g_off[e] - m0;
    if (mrows > BM) mrows = BM;
    const int n0 = blockIdx.x * BN;

    extern __shared__ char smem[];
    const uint32_t sb = smem_u32(smem);
    const int tid = threadIdx.x, wid = tid >> 5, lane = tid & 31;
    const int warp_m = wid & 1, warp_n = wid >> 1;     // 2 x 4 warps of 64x64

    if (ADD_BIAS && tid < 64)
        ((float4*)(smem + BIAS_OFF))[tid] =
            *(const float4*)&bias[(size_t)e * N + n0 + tid * 4];

    // ---- load mapping ----
    const int rA  = tid >> 2;              // A rows rA, rA+64
    const int cch = (tid & 3) * 8;         // fp32 col offset in k-tile
    const uint32_t cby = (uint32_t)(tid & 3) * 16;
    const uint32_t sdA0 = (uint32_t)(rA * SROW) + cby;
    const uint32_t sdA1 = sdA0 + 64 * SROW;
    const bool aok0 = rA < mrows, aok1 = (rA + 64) < mrows;
    const uint32_t szA0 = aok0 ? 16u : 0u, szA1 = aok1 ? 16u : 0u;
    const float4 z4 = make_float4(0.f, 0.f, 0.f, 0.f);

    const float* Afp0 = Af + (size_t)(row0 + rA) * K + cch;
    const float* Afp1 = Af + (size_t)(row0 + rA + 64) * K + cch;
    const char*  Ahp0 = (const char*)(Ahi + (size_t)(row0 + rA) * K + cch);
    const char*  Ahp1 = (const char*)(Ahi + (size_t)(row0 + rA + 64) * K + cch);
    const char*  Alp0 = (const char*)(Alo + (size_t)(row0 + rA) * K + cch);
    const char*  Alp1 = (const char*)(Alo + (size_t)(row0 + rA + 64) * K + cch);
    // B: 4 row chunks rA + {0,64,128,192}
    const float* Bbase = Bf + ((size_t)e * N + n0 + rA) * K + cch;
    const size_t Bstep = (size_t)64 * K;

    // -------- prologue: stage kt=0 into buffer 0 --------
    if (A_BF16) {
        cpa16(sb + sdA0, Ahp0, szA0);
        cpa16(sb + sdA1, Ahp1, szA1);
        cpa16(sb + OFF_ALO + sdA0, Alp0, szA0);
        cpa16(sb + OFF_ALO + sdA1, Alp1, szA1);
        CP_COMMIT();
    } else {
        float4 a0 = aok0 ? *(const float4*)Afp0 : z4;
        float4 a1 = aok0 ? *(const float4*)(Afp0 + 4) : z4;
        float4 a2 = aok1 ? *(const float4*)Afp1 : z4;
        float4 a3 = aok1 ? *(const float4*)(Afp1 + 4) : z4;
        split_sts(sb + sdA0, sb + OFF_ALO + sdA0, a0, a1);
        split_sts(sb + sdA1, sb + OFF_ALO + sdA1, a2, a3);
    }
#pragma unroll
    for (int q = 0; q < 4; ++q) {
        const float* bp = Bbase + (size_t)q * Bstep;
        float4 u0 = *(const float4*)bp;
        float4 u1 = *(const float4*)(bp + 4);
        const uint32_t sd = sdA0 + (uint32_t)q * (64 * SROW);
        split_sts(sb + OFF_BHI + sd, sb + OFF_BLO + sd, u0, u1);
    }
    if (A_BF16) CP_WAIT0();
    __syncthreads();

    float acc[4][8][4];
#pragma unroll
    for (int mi = 0; mi < 4; ++mi)
#pragma unroll
        for (int nj = 0; nj < 8; ++nj)
#pragma unroll
            for (int q = 0; q < 4; ++q) acc[mi][nj][q] = 0.f;

    const uint32_t a_off = (uint32_t)(warp_m * 64 + (lane & 15)) * SROW +
                           ((lane >> 4) * 16);
    const uint32_t b_off = (uint32_t)(warp_n * 64 + (lane & 7) +
                                      ((lane >> 4) & 1) * 8) * SROW +
                           (((lane >> 3) & 1) * 16);

    const int nk = K >> 5;
    for (int kt = 0; kt < nk; ++kt) {
        const uint32_t stg  = sb + (uint32_t)(kt & 1) * STAGEB;
        const uint32_t nstg = sb + (uint32_t)((kt + 1) & 1) * STAGEB;
        const bool more = (kt + 1 < nk);
        const int ko = (kt + 1) * 32;

        // A prefetch for kt+1 (async or regs) — overlaps the MMA phase below.
        float4 a0, a1, a2, a3;
        if (more) {
            if (A_BF16) {
                cpa16(nstg + sdA0, Ahp0 + ko * 2, szA0);
                cpa16(nstg + sdA1, Ahp1 + ko * 2, szA1);
                cpa16(nstg + OFF_ALO + sdA0, Alp0 + ko * 2, szA0);
                cpa16(nstg + OFF_ALO + sdA1, Alp1 + ko * 2, szA1);
                CP_COMMIT();
            } else {
                a0 = aok0 ? *(const float4*)(Afp0 + ko) : z4;
                a1 = aok0 ? *(const float4*)(Afp0 + ko + 4) : z4;
                a2 = aok1 ? *(const float4*)(Afp1 + ko) : z4;
                a3 = aok1 ? *(const float4*)(Afp1 + ko + 4) : z4;
            }
        }

        // ------------------------- MMA phase (2 x k16) ----------------------
#pragma unroll
        for (int k16 = 0; k16 < 2; ++k16) {
            const uint32_t kb = k16 * 32;
            uint32_t ah[4][4], ax[4][4], bb[4][4];
#pragma unroll
            for (int mi = 0; mi < 4; ++mi)
                ldsm4(ah[mi], stg + a_off + kb + mi * 16 * SROW);
#pragma unroll
            for (int bj = 0; bj < 4; ++bj)
                ldsm4(bb[bj], stg + OFF_BHI + b_off + kb + bj * 16 * SROW);
            // hh
#pragma unroll
            for (int mi = 0; mi < 4; ++mi)
#pragma unroll
                for (int nj = 0; nj < 8; ++nj)
                    mma16816(acc[mi][nj], ah[mi], &bb[nj >> 1][(nj & 1) * 2]);
            // lh: al * bh
#pragma unroll
            for (int mi = 0; mi < 4; ++mi)
                ldsm4(ax[mi], stg + OFF_ALO + a_off + kb + mi * 16 * SROW);
#pragma unroll
            for (int mi = 0; mi < 4; ++mi)
#pragma unroll
                for (int nj = 0; nj < 8; ++nj)
                    mma16816(acc[mi][nj], ax[mi], &bb[nj >> 1][(nj & 1) * 2]);
            // hl: ah * bl  (reload bb from lo tile)
#pragma unroll
            for (int bj = 0; bj < 4; ++bj)
                ldsm4(bb[bj], stg + OFF_BLO + b_off + kb + bj * 16 * SROW);
#pragma unroll
            for (int mi = 0; mi < 4; ++mi)
#pragma unroll
                for (int nj = 0; nj < 8; ++nj)
                    mma16816(acc[mi][nj], ah[mi], &bb[nj >> 1][(nj & 1) * 2]);
        }

        // --------------------- stage kt+1 (A regs + B split) ----------------
        if (more) {
            if (!A_BF16) {
                split_sts(nstg + sdA0, nstg + OFF_ALO + sdA0, a0, a1);
                split_sts(nstg + sdA1, nstg + OFF_ALO + sdA1, a2, a3);
            }
#pragma unroll
            for (int q = 0; q < 4; ++q) {
                const float* bp = Bbase + (size_t)q * Bstep + ko;
                float4 u0 = *(const float4*)bp;
                float4 u1 = *(const float4*)(bp + 4);
                const uint32_t sd = sdA0 + (uint32_t)q * (64 * SROW);
                split_sts(nstg + OFF_BHI + sd, nstg + OFF_BLO + sd, u0, u1);
            }
            if (A_BF16) CP_WAIT0();
        }
        __syncthreads();
    }

    // ------------------------------ epilogue --------------------------------
    const float* bs = (const float*)(smem + BIAS_OFF);
    uint32_t* yh32 = (uint32_t*)g_yhi;
    uint32_t* yl32 = (uint32_t*)g_ylo;
#pragma unroll
    for (int mi = 0; mi < 4; ++mi) {
        const int r = warp_m * 64 + mi * 16 + (lane >> 2);
#pragma unroll
        for (int nj = 0; nj < 8; ++nj) {
            const int c = warp_n * 64 + nj * 8 + (lane & 3) * 2;
            float2 v0 = make_float2(acc[mi][nj][0], acc[mi][nj][1]);
            float2 v1 = make_float2(acc[mi][nj][2], acc[mi][nj][3]);
            if (ADD_BIAS) {
                const float b0 = bs[c], b1 = bs[c + 1];
                v0.x += b0; v0.y += b1;
                v1.x += b0; v1.y += b1;
            }
            if (SPLIT_OUT) {
                if (r < mrows) {
                    const size_t ix = ((size_t)(row0 + r) * N + n0 + c) >> 1;
                    yh32[ix] = prmt_hi(v0.x, v0.y);
                    yl32[ix] = pack_lo(v0.x - trunc16f(v0.x),
                                       v0.y - trunc16f(v0.y));
                }
                if (r + 8 < mrows) {
                    const size_t ix = ((size_t)(row0 + r + 8) * N + n0 + c) >> 1;
                    yh32[ix] = prmt_hi(v1.x, v1.y);
                    yl32[ix] = pack_lo(v1.x - trunc16f(v1.x),
                                       v1.y - trunc16f(v1.y));
                }
            } else {
                if (r < mrows)
                    *(float2*)&Cf[(size_t)(row0 + r) * N + n0 + c] = v0;
                if (r + 8 < mrows)
                    *(float2*)&Cf[(size_t)(row0 + r + 8) * N + n0 + c] = v1;
            }
        }
    }
}

// ------------------------------- launch -------------------------------------
extern "C" void kernel_launch(void* const* d_in, const int* in_sizes, int n_in,
                              void* d_out, int out_size) {
    const float* inp  = (const float*)d_in[0];
    const int*   cnt  = (const int*)  d_in[1];
    const float* wgt  = (const float*)d_in[2];
    const float* bias = (const float*)d_in[3];
    const float* comp = (const float*)d_in[4];
    float* out = (float*)d_out;

    const int E     = in_sizes[1];
    const int D_out = in_sizes[3] / E;
    const int D_in  = in_sizes[2] / in_sizes[3];
    const int T     = in_sizes[0] / D_in;
    const int S     = in_sizes[4] / in_sizes[3];
    const int maxtiles = T / BM + E;

    cudaFuncSetAttribute(moe_hmma<true, false, true>,
                         cudaFuncAttributeMaxDynamicSharedMemorySize, SMEM_TOTAL);
    cudaFuncSetAttribute(moe_hmma<false, true, false>,
                         cudaFuncAttributeMaxDynamicSharedMemorySize, SMEM_TOTAL);

    __nv_bfloat16 *yhi, *ylo;
    cudaGetSymbolAddress((void**)&yhi, g_yhi);
    cudaGetSymbolAddress((void**)&ylo, g_ylo);

    setup_kernel<<<1, 1>>>(cnt, E);

    // GEMM1: y = x @ W^T + b  (A fp32 split in-loop; y emitted split bf16)
    moe_hmma<true, false, true><<<dim3(D_out / BN, maxtiles), NTH, SMEM_TOTAL>>>(
        inp, nullptr, nullptr, wgt, bias, nullptr, D_in, D_out);
    // GEMM2: out = y @ C^T  (A pre-split via cp.async; comp split in-loop)
    moe_hmma<false, true, false><<<dim3(S / BN, maxtiles), NTH, SMEM_TOTAL>>>(
        nullptr, yhi, ylo, comp, nullptr, out, D_out, S);
}

// round 10
// speedup vs baseline: 1.3359x; 1.3359x over previous
#include <cuda_runtime.h>
#include <cuda_fp16.h>
#include <cstdint>

// ---------------------------------------------------------------------------
// FMoELinearProj via legacy HMMA (mma.sync.m16n8k16.f16).
// R9: 2-term fp16 scheme. A = ah + al (two fp16 digits, ~22-bit exact);
// B rounded to ONE fp16 digit (rel err ~2^-12 RMS, randomized over K).
// out = ah*bh + al*bh  => 2 MMAs per tile instead of 3, no B-lo tile.
// CTA 128x128, 256 thr, 8 warps of 32x64, 2-stage smem (3 tiles/stage),
// 2 CTAs/SM. GEMM1 emits y as two fp16 digits; GEMM2 pulls via cp.async.
// ---------------------------------------------------------------------------

#define BM 128
#define BN 128
#define NTH 256
#define SROW 80                       // padded smem row (64B data + 16B pad)
#define TILEB (128 * SROW)            // 10240 B per fp16 tile
#define OFF_ALO TILEB
#define OFF_BHI (2 * TILEB)
#define STAGEB (3 * TILEB)            // Ahi, Alo, Bhi
#define BIAS_OFF (2 * STAGEB)         // 61440
#define SMEM_TOTAL (BIAS_OFF + 512)

__device__ int  g_off[65];
__device__ int2 g_tiles[1024];
__device__ int  g_ntiles;
__device__ __half g_yhi[8192ull * 4096];
__device__ __half g_ylo[8192ull * 4096];

// ------------------------------- helpers -----------------------------------
__device__ __forceinline__ uint32_t smem_u32(const void* p) {
    uint32_t a;
    asm("{ .reg .u64 t; cvta.to.shared.u64 t, %1; cvt.u32.u64 %0, t; }"
        : "=r"(a) : "l"(p));
    return a;
}
__device__ __forceinline__ void ldsm4(uint32_t* r, uint32_t addr) {
    asm volatile("ldmatrix.sync.aligned.m8n8.x4.shared.b16 {%0,%1,%2,%3}, [%4];"
                 : "=r"(r[0]), "=r"(r[1]), "=r"(r[2]), "=r"(r[3]) : "r"(addr));
}
__device__ __forceinline__ void mma16816(float* c, const uint32_t* a,
                                         const uint32_t* b) {
    asm volatile(
        "mma.sync.aligned.m16n8k16.row.col.f32.f16.f16.f32 "
        "{%0,%1,%2,%3}, {%4,%5,%6,%7}, {%8,%9}, {%0,%1,%2,%3};"
        : "+f"(c[0]), "+f"(c[1]), "+f"(c[2]), "+f"(c[3])
        : "r"(a[0]), "r"(a[1]), "r"(a[2]), "r"(a[3]), "r"(b[0]), "r"(b[1]));
}
__device__ __forceinline__ void cpa16(uint32_t dst, const void* src,
                                      uint32_t ssize) {
    asm volatile("cp.async.cg.shared.global [%0], [%1], 16, %2;"
                 :: "r"(dst), "l"(src), "r"(ssize) : "memory");
}
#define CP_COMMIT() asm volatile("cp.async.commit_group;" ::: "memory")
#define CP_WAIT0()  asm volatile("cp.async.wait_group 0;" ::: "memory")

__device__ __forceinline__ void sts128(uint32_t a, uint32_t r0, uint32_t r1,
                                       uint32_t r2, uint32_t r3) {
    asm volatile("st.shared.v4.b32 [%0], {%1, %2, %3, %4};"
                 :: "r"(a), "r"(r0), "r"(r1), "r"(r2), "r"(r3) : "memory");
}
// pack two fp32 -> fp16x2 (round-to-nearest)
__device__ __forceinline__ uint32_t h2rn(float e0, float e1) {
    uint32_t d;
    asm("cvt.rn.f16x2.f32 %0, %1, %2;" : "=r"(d) : "f"(e1), "f"(e0));
    return d;
}
__device__ __forceinline__ float h2f_lo(uint32_t h) {
    float f;
    asm("{ .reg .f16 a, b; mov.b32 {a, b}, %1; cvt.f32.f16 %0, a; }"
        : "=f"(f) : "r"(h));
    return f;
}
__device__ __forceinline__ float h2f_hi(uint32_t h) {
    float f;
    asm("{ .reg .f16 a, b; mov.b32 {a, b}, %1; cvt.f32.f16 %0, b; }"
        : "=f"(f) : "r"(h));
    return f;
}
// Split 8 fp32 into fp16 hi digits + fp16 lo residual digits; store 16B each.
__device__ __forceinline__ void split_sts_a(uint32_t hib, uint32_t lob,
                                            float4 u0, float4 u1) {
    uint32_t h0 = h2rn(u0.x, u0.y);
    uint32_t h1 = h2rn(u0.z, u0.w);
    uint32_t h2 = h2rn(u1.x, u1.y);
    uint32_t h3 = h2rn(u1.z, u1.w);
    uint32_t l0 = h2rn(u0.x - h2f_lo(h0), u0.y - h2f_hi(h0));
    uint32_t l1 = h2rn(u0.z - h2f_lo(h1), u0.w - h2f_hi(h1));
    uint32_t l2 = h2rn(u1.x - h2f_lo(h2), u1.y - h2f_hi(h2));
    uint32_t l3 = h2rn(u1.z - h2f_lo(h3), u1.w - h2f_hi(h3));
    sts128(hib, h0, h1, h2, h3);
    sts128(lob, l0, l1, l2, l3);
}
// Round 8 fp32 to single fp16 digits; store 16B.
__device__ __forceinline__ void round_sts_b(uint32_t hib, float4 u0, float4 u1) {
    sts128(hib, h2rn(u0.x, u0.y), h2rn(u0.z, u0.w),
                h2rn(u1.x, u1.y), h2rn(u1.z, u1.w));
}

// ------------------------------ setup kernel -------------------------------
__global__ void setup_kernel(const int* __restrict__ counts, int E) {
    if (threadIdx.x == 0 && blockIdx.x == 0) {
        int off = 0, nt = 0;
        for (int e = 0; e < E; ++e) {
            g_off[e] = off;
            int c = counts[e];
            for (int m = 0; m < c; m += BM) { g_tiles[nt].x = e; g_tiles[nt].y = m; ++nt; }
            off += c;
        }
        g_off[E] = off;
        g_ntiles = nt;
    }
}

// ------------------------------ main GEMM kernel ---------------------------
// C[row, n] = sum_k A[row, k] * B[e, n, k] (+ bias).
// A_F16: A pre-split (g_yhi/g_ylo) via cp.async; else fp32 split in-loop.
// SPLIT_OUT: write C as two fp16 digits into g_yhi/g_ylo; else fp32 to Cf.
template <bool ADD_BIAS, bool A_F16, bool SPLIT_OUT>
__global__ __launch_bounds__(NTH, 2)
void moe_hmma(const float* __restrict__ Af,
              const __half* __restrict__ Ahi,
              const __half* __restrict__ Alo,
              const float* __restrict__ Bf,
              const float* __restrict__ bias, float* __restrict__ Cf,
              int K, int N)
{
    const int tile = blockIdx.y;
    if (tile >= g_ntiles) return;
    const int e    = g_tiles[tile].x;
    const int m0   = g_tiles[tile].y;
    const int row0 = g_off[e] + m0;
    int mrows = g_off[e + 1] - g_off[e] - m0;
    if (mrows > BM) mrows = BM;
    const int n0 = blockIdx.x * BN;

    extern __shared__ char smem[];
    const uint32_t sb = smem_u32(smem);
    const int tid = threadIdx.x, wid = tid >> 5, lane = tid & 31;
    const int warp_m = wid & 3, warp_n = wid >> 2;   // 4 x 2 warps of 32x64

    if (ADD_BIAS && tid < 32)
        ((float4*)(smem + BIAS_OFF))[tid] =
            *(const float4*)&bias[(size_t)e * N + n0 + tid * 4];

    // ---- load mapping: 2 chunks (8 fp32) per thread per tile per operand ---
    const int r0c = tid >> 2;              // rows r0c and r0c+64
    const int ccol = (tid & 3) * 8;        // fp32 column offset in k-tile
    const uint32_t sdst0 = (uint32_t)(r0c * SROW) + (tid & 3) * 16;
    const uint32_t sdst1 = sdst0 + 64 * SROW;
    const bool aok0 = r0c < mrows;
    const bool aok1 = (r0c + 64) < mrows;
    const float4 z4 = make_float4(0.f, 0.f, 0.f, 0.f);

    const float* Afp0 = Af + (size_t)(row0 + r0c) * K + ccol;
    const float* Afp1 = Af + (size_t)(row0 + r0c + 64) * K + ccol;
    const char*  Ahp0 = (const char*)(Ahi + (size_t)(row0 + r0c) * K + ccol);
    const char*  Ahp1 = (const char*)(Ahi + (size_t)(row0 + r0c + 64) * K + ccol);
    const char*  Alp0 = (const char*)(Alo + (size_t)(row0 + r0c) * K + ccol);
    const char*  Alp1 = (const char*)(Alo + (size_t)(row0 + r0c + 64) * K + ccol);
    const float* Bfp0 = Bf + ((size_t)e * N + n0 + r0c) * K + ccol;
    const float* Bfp1 = Bf + ((size_t)e * N + n0 + r0c + 64) * K + ccol;
    const uint32_t sz0 = aok0 ? 16u : 0u, sz1 = aok1 ? 16u : 0u;

    float4 a00, a01, a10, a11, b00, b01, b10, b11;

    // -------- prologue: stage kt=0 into buffer 0 --------
    if (A_F16) {
        cpa16(sb + sdst0, Ahp0, sz0);
        cpa16(sb + sdst1, Ahp1, sz1);
        cpa16(sb + OFF_ALO + sdst0, Alp0, sz0);
        cpa16(sb + OFF_ALO + sdst1, Alp1, sz1);
        CP_COMMIT();
    } else {
        a00 = aok0 ? *(const float4*)Afp0 : z4;
        a01 = aok0 ? *(const float4*)(Afp0 + 4) : z4;
        a10 = aok1 ? *(const float4*)Afp1 : z4;
        a11 = aok1 ? *(const float4*)(Afp1 + 4) : z4;
    }
    b00 = *(const float4*)Bfp0;
    b01 = *(const float4*)(Bfp0 + 4);
    b10 = *(const float4*)Bfp1;
    b11 = *(const float4*)(Bfp1 + 4);
    if (!A_F16) {
        split_sts_a(sb + sdst0, sb + OFF_ALO + sdst0, a00, a01);
        split_sts_a(sb + sdst1, sb + OFF_ALO + sdst1, a10, a11);
    }
    round_sts_b(sb + OFF_BHI + sdst0, b00, b01);
    round_sts_b(sb + OFF_BHI + sdst1, b10, b11);
    if (A_F16) CP_WAIT0();
    __syncthreads();

    float acc[2][8][4];
#pragma unroll
    for (int mi = 0; mi < 2; ++mi)
#pragma unroll
        for (int nj = 0; nj < 8; ++nj)
#pragma unroll
            for (int q = 0; q < 4; ++q) acc[mi][nj][q] = 0.f;

    const uint32_t a_off = (uint32_t)(warp_m * 32 + (lane & 15)) * SROW +
                           ((lane >> 4) * 16);
    const uint32_t b_off = (uint32_t)(warp_n * 64 + (lane & 7) +
                                      ((lane >> 4) & 1) * 8) * SROW +
                           (((lane >> 3) & 1) * 16);

    const int nk = K >> 5;
    for (int kt = 0; kt < nk; ++kt) {
        const uint32_t stg  = sb + (uint32_t)(kt & 1) * STAGEB;
        const uint32_t nstg = sb + (uint32_t)((kt + 1) & 1) * STAGEB;
        const bool more = (kt + 1 < nk);
        if (more) {
            const int ko = (kt + 1) * 32;
            if (A_F16) {
                cpa16(nstg + sdst0, Ahp0 + ko * 2, sz0);
                cpa16(nstg + sdst1, Ahp1 + ko * 2, sz1);
                cpa16(nstg + OFF_ALO + sdst0, Alp0 + ko * 2, sz0);
                cpa16(nstg + OFF_ALO + sdst1, Alp1 + ko * 2, sz1);
                CP_COMMIT();
            } else {
                a00 = aok0 ? *(const float4*)(Afp0 + ko) : z4;
                a01 = aok0 ? *(const float4*)(Afp0 + ko + 4) : z4;
                a10 = aok1 ? *(const float4*)(Afp1 + ko) : z4;
                a11 = aok1 ? *(const float4*)(Afp1 + ko + 4) : z4;
            }
            b00 = *(const float4*)(Bfp0 + ko);
            b01 = *(const float4*)(Bfp0 + ko + 4);
            b10 = *(const float4*)(Bfp1 + ko);
            b11 = *(const float4*)(Bfp1 + ko + 4);
        }
#pragma unroll
        for (int k16 = 0; k16 < 2; ++k16) {
            const uint32_t kb = k16 * 32;
            uint32_t ah[2][4], al[2][4], bh[4][4];
            ldsm4(ah[0], stg + a_off + kb);
            ldsm4(ah[1], stg + a_off + kb + 16 * SROW);
            ldsm4(al[0], stg + OFF_ALO + a_off + kb);
            ldsm4(al[1], stg + OFF_ALO + a_off + kb + 16 * SROW);
#pragma unroll
            for (int bj = 0; bj < 4; ++bj)
                ldsm4(bh[bj], stg + OFF_BHI + b_off + kb + bj * 16 * SROW);
            // term 1: ah * bh
#pragma unroll
            for (int mi = 0; mi < 2; ++mi)
#pragma unroll
                for (int nj = 0; nj < 8; ++nj)
                    mma16816(acc[mi][nj], ah[mi], &bh[nj >> 1][(nj & 1) * 2]);
            // term 2: al * bh
#pragma unroll
            for (int mi = 0; mi < 2; ++mi)
#pragma unroll
                for (int nj = 0; nj < 8; ++nj)
                    mma16816(acc[mi][nj], al[mi], &bh[nj >> 1][(nj & 1) * 2]);
        }
        if (more) {
            if (!A_F16) {
                split_sts_a(nstg + sdst0, nstg + OFF_ALO + sdst0, a00, a01);
                split_sts_a(nstg + sdst1, nstg + OFF_ALO + sdst1, a10, a11);
            }
            round_sts_b(nstg + OFF_BHI + sdst0, b00, b01);
            round_sts_b(nstg + OFF_BHI + sdst1, b10, b11);
            if (A_F16) CP_WAIT0();
        }
        __syncthreads();
    }

    // ------------------------------ epilogue --------------------------------
    const float* bs = (const float*)(smem + BIAS_OFF);
    uint32_t* yh32 = (uint32_t*)g_yhi;
    uint32_t* yl32 = (uint32_t*)g_ylo;
#pragma unroll
    for (int mi = 0; mi < 2; ++mi) {
        const int r = warp_m * 32 + mi * 16 + (lane >> 2);
#pragma unroll
        for (int nj = 0; nj < 8; ++nj) {
            const int c = warp_n * 64 + nj * 8 + (lane & 3) * 2;
            float2 v0 = make_float2(acc[mi][nj][0], acc[mi][nj][1]);
            float2 v1 = make_float2(acc[mi][nj][2], acc[mi][nj][3]);
            if (ADD_BIAS) {
                const float b0 = bs[c], b1 = bs[c + 1];
                v0.x += b0; v0.y += b1;
                v1.x += b0; v1.y += b1;
            }
            if (SPLIT_OUT) {
                if (r < mrows) {
                    const size_t ix = ((size_t)(row0 + r) * N + n0 + c) >> 1;
                    uint32_t h = h2rn(v0.x, v0.y);
                    yh32[ix] = h;
                    yl32[ix] = h2rn(v0.x - h2f_lo(h), v0.y - h2f_hi(h));
                }
                if (r + 8 < mrows) {
                    const size_t ix = ((size_t)(row0 + r + 8) * N + n0 + c) >> 1;
                    uint32_t h = h2rn(v1.x, v1.y);
                    yh32[ix] = h;
                    yl32[ix] = h2rn(v1.x - h2f_lo(h), v1.y - h2f_hi(h));
                }
            } else {
                if (r < mrows)
                    *(float2*)&Cf[(size_t)(row0 + r) * N + n0 + c] = v0;
                if (r + 8 < mrows)
                    *(float2*)&Cf[(size_t)(row0 + r + 8) * N + n0 + c] = v1;
            }
        }
    }
}

// ------------------------------- launch -------------------------------------
extern "C" void kernel_launch(void* const* d_in, const int* in_sizes, int n_in,
                              void* d_out, int out_size) {
    const float* inp  = (const float*)d_in[0];
    const int*   cnt  = (const int*)  d_in[1];
    const float* wgt  = (const float*)d_in[2];
    const float* bias = (const float*)d_in[3];
    const float* comp = (const float*)d_in[4];
    float* out = (float*)d_out;

    const int E     = in_sizes[1];
    const int D_out = in_sizes[3] / E;
    const int D_in  = in_sizes[2] / in_sizes[3];
    const int T     = in_sizes[0] / D_in;
    const int S     = in_sizes[4] / in_sizes[3];
    const int maxtiles = T / BM + E;

    cudaFuncSetAttribute(moe_hmma<true, false, true>,
                         cudaFuncAttributeMaxDynamicSharedMemorySize, SMEM_TOTAL);
    cudaFuncSetAttribute(moe_hmma<false, true, false>,
                         cudaFuncAttributeMaxDynamicSharedMemorySize, SMEM_TOTAL);

    __half *yhi, *ylo;
    cudaGetSymbolAddress((void**)&yhi, g_yhi);
    cudaGetSymbolAddress((void**)&ylo, g_ylo);

    setup_kernel<<<1, 1>>>(cnt, E);

    // GEMM1: y = x @ W^T + b  (A fp32 split in-loop; y emitted as 2 fp16 digits)
    moe_hmma<true, false, true><<<dim3(D_out / BN, maxtiles), NTH, SMEM_TOTAL>>>(
        inp, nullptr, nullptr, wgt, bias, nullptr, D_in, D_out);
    // GEMM2: out = y @ C^T  (A pre-split via cp.async; comp rounded in-loop)
    moe_hmma<false, true, false><<<dim3(S / BN, maxtiles), NTH, SMEM_TOTAL>>>(
        nullptr, yhi, ylo, comp, nullptr, out, D_out, S);
}

// round 11
// speedup vs baseline: 2.2359x; 1.6737x over previous
#include <cuda_runtime.h>
#include <cuda_fp16.h>
#include <cstdint>

// ---------------------------------------------------------------------------
// FMoELinearProj via legacy HMMA (mma.sync.m16n8k16.f16).
// R10: single fp16 digit for BOTH operands — 1 MMA per tile position.
// Error model: 4 independent rounding sources (x, W, y, comp), each ~2e-4
// => total ~4-6e-4 < 1e-3 threshold (R9 measured 2.9e-4 with 2 sources).
// CTA 128x128, 256 thr, 8 warps of 32x64, 2-stage smem (2 tiles/stage),
// 2 CTAs/SM. GEMM1 emits y as fp16; GEMM2 pulls it via cp.async.
// ---------------------------------------------------------------------------

#define BM 128
#define BN 128
#define NTH 256
#define SROW 80                       // padded smem row (64B data + 16B pad)
#define TILEB (128 * SROW)            // 10240 B per fp16 tile
#define OFF_BHI TILEB
#define STAGEB (2 * TILEB)            // Ahi, Bhi
#define BIAS_OFF (2 * STAGEB)         // 40960
#define SMEM_TOTAL (BIAS_OFF + 512)

__device__ int  g_off[65];
__device__ int2 g_tiles[1024];
__device__ int  g_ntiles;
__device__ __half g_yh[8192ull * 4096];

// ------------------------------- helpers -----------------------------------
__device__ __forceinline__ uint32_t smem_u32(const void* p) {
    uint32_t a;
    asm("{ .reg .u64 t; cvta.to.shared.u64 t, %1; cvt.u32.u64 %0, t; }"
        : "=r"(a) : "l"(p));
    return a;
}
__device__ __forceinline__ void ldsm4(uint32_t* r, uint32_t addr) {
    asm volatile("ldmatrix.sync.aligned.m8n8.x4.shared.b16 {%0,%1,%2,%3}, [%4];"
                 : "=r"(r[0]), "=r"(r[1]), "=r"(r[2]), "=r"(r[3]) : "r"(addr));
}
__device__ __forceinline__ void mma16816(float* c, const uint32_t* a,
                                         const uint32_t* b) {
    asm volatile(
        "mma.sync.aligned.m16n8k16.row.col.f32.f16.f16.f32 "
        "{%0,%1,%2,%3}, {%4,%5,%6,%7}, {%8,%9}, {%0,%1,%2,%3};"
        : "+f"(c[0]), "+f"(c[1]), "+f"(c[2]), "+f"(c[3])
        : "r"(a[0]), "r"(a[1]), "r"(a[2]), "r"(a[3]), "r"(b[0]), "r"(b[1]));
}
__device__ __forceinline__ void cpa16(uint32_t dst, const void* src,
                                      uint32_t ssize) {
    asm volatile("cp.async.cg.shared.global [%0], [%1], 16, %2;"
                 :: "r"(dst), "l"(src), "r"(ssize) : "memory");
}
#define CP_COMMIT() asm volatile("cp.async.commit_group;" ::: "memory")
#define CP_WAIT0()  asm volatile("cp.async.wait_group 0;" ::: "memory")

__device__ __forceinline__ void sts128(uint32_t a, uint32_t r0, uint32_t r1,
                                       uint32_t r2, uint32_t r3) {
    asm volatile("st.shared.v4.b32 [%0], {%1, %2, %3, %4};"
                 :: "r"(a), "r"(r0), "r"(r1), "r"(r2), "r"(r3) : "memory");
}
// pack two fp32 -> fp16x2 (round-to-nearest)
__device__ __forceinline__ uint32_t h2rn(float e0, float e1) {
    uint32_t d;
    asm("cvt.rn.f16x2.f32 %0, %1, %2;" : "=r"(d) : "f"(e1), "f"(e0));
    return d;
}
// Round 8 fp32 to fp16 digits; store 16B.
__device__ __forceinline__ void round_sts(uint32_t dst, float4 u0, float4 u1) {
    sts128(dst, h2rn(u0.x, u0.y), h2rn(u0.z, u0.w),
                h2rn(u1.x, u1.y), h2rn(u1.z, u1.w));
}

// ------------------------------ setup kernel -------------------------------
__global__ void setup_kernel(const int* __restrict__ counts, int E) {
    if (threadIdx.x == 0 && blockIdx.x == 0) {
        int off = 0, nt = 0;
        for (int e = 0; e < E; ++e) {
            g_off[e] = off;
            int c = counts[e];
            for (int m = 0; m < c; m += BM) { g_tiles[nt].x = e; g_tiles[nt].y = m; ++nt; }
            off += c;
        }
        g_off[E] = off;
        g_ntiles = nt;
    }
}

// ------------------------------ main GEMM kernel ---------------------------
// C[row, n] = sum_k A[row, k] * B[e, n, k] (+ bias).
// A_F16: A pre-rounded (g_yh), fetched via cp.async; else fp32 rounded in-loop.
// F16_OUT: write C as fp16 into g_yh; else fp32 to Cf.
template <bool ADD_BIAS, bool A_F16, bool F16_OUT>
__global__ __launch_bounds__(NTH, 2)
void moe_hmma(const float* __restrict__ Af,
              const __half* __restrict__ Ah,
              const float* __restrict__ Bf,
              const float* __restrict__ bias, float* __restrict__ Cf,
              int K, int N)
{
    const int tile = blockIdx.y;
    if (tile >= g_ntiles) return;
    const int e    = g_tiles[tile].x;
    const int m0   = g_tiles[tile].y;
    const int row0 = g_off[e] + m0;
    int mrows = g_off[e + 1] - g_off[e] - m0;
    if (mrows > BM) mrows = BM;
    const int n0 = blockIdx.x * BN;

    extern __shared__ char smem[];
    const uint32_t sb = smem_u32(smem);
    const int tid = threadIdx.x, wid = tid >> 5, lane = tid & 31;
    const int warp_m = wid & 3, warp_n = wid >> 2;   // 4 x 2 warps of 32x64

    if (ADD_BIAS && tid < 32)
        ((float4*)(smem + BIAS_OFF))[tid] =
            *(const float4*)&bias[(size_t)e * N + n0 + tid * 4];

    // ---- load mapping: 2 chunks (8 fp32 / 16B fp16) per thread per tile ----
    const int r0c = tid >> 2;              // rows r0c and r0c+64
    const int ccol = (tid & 3) * 8;        // fp32 column offset in k-tile
    const uint32_t sdst0 = (uint32_t)(r0c * SROW) + (tid & 3) * 16;
    const uint32_t sdst1 = sdst0 + 64 * SROW;
    const bool aok0 = r0c < mrows;
    const bool aok1 = (r0c + 64) < mrows;
    const float4 z4 = make_float4(0.f, 0.f, 0.f, 0.f);

    const float* Afp0 = Af + (size_t)(row0 + r0c) * K + ccol;
    const float* Afp1 = Af + (size_t)(row0 + r0c + 64) * K + ccol;
    const char*  Ahp0 = (const char*)(Ah + (size_t)(row0 + r0c) * K + ccol);
    const char*  Ahp1 = (const char*)(Ah + (size_t)(row0 + r0c + 64) * K + ccol);
    const float* Bfp0 = Bf + ((size_t)e * N + n0 + r0c) * K + ccol;
    const float* Bfp1 = Bf + ((size_t)e * N + n0 + r0c + 64) * K + ccol;
    const uint32_t sz0 = aok0 ? 16u : 0u, sz1 = aok1 ? 16u : 0u;

    float4 a00, a01, a10, a11, b00, b01, b10, b11;

    // -------- prologue: stage kt=0 into buffer 0 --------
    if (A_F16) {
        cpa16(sb + sdst0, Ahp0, sz0);
        cpa16(sb + sdst1, Ahp1, sz1);
        CP_COMMIT();
    } else {
        a00 = aok0 ? *(const float4*)Afp0 : z4;
        a01 = aok0 ? *(const float4*)(Afp0 + 4) : z4;
        a10 = aok1 ? *(const float4*)Afp1 : z4;
        a11 = aok1 ? *(const float4*)(Afp1 + 4) : z4;
    }
    b00 = *(const float4*)Bfp0;
    b01 = *(const float4*)(Bfp0 + 4);
    b10 = *(const float4*)Bfp1;
    b11 = *(const float4*)(Bfp1 + 4);
    if (!A_F16) {
        round_sts(sb + sdst0, a00, a01);
        round_sts(sb + sdst1, a10, a11);
    }
    round_sts(sb + OFF_BHI + sdst0, b00, b01);
    round_sts(sb + OFF_BHI + sdst1, b10, b11);
    if (A_F16) CP_WAIT0();
    __syncthreads();

    float acc[2][8][4];
#pragma unroll
    for (int mi = 0; mi < 2; ++mi)
#pragma unroll
        for (int nj = 0; nj < 8; ++nj)
#pragma unroll
            for (int q = 0; q < 4; ++q) acc[mi][nj][q] = 0.f;

    const uint32_t a_off = (uint32_t)(warp_m * 32 + (lane & 15)) * SROW +
                           ((lane >> 4) * 16);
    const uint32_t b_off = (uint32_t)(warp_n * 64 + (lane & 7) +
                                      ((lane >> 4) & 1) * 8) * SROW +
                           (((lane >> 3) & 1) * 16);

    const int nk = K >> 5;
    for (int kt = 0; kt < nk; ++kt) {
        const uint32_t stg  = sb + (uint32_t)(kt & 1) * STAGEB;
        const uint32_t nstg = sb + (uint32_t)((kt + 1) & 1) * STAGEB;
        const bool more = (kt + 1 < nk);
        if (more) {
            const int ko = (kt + 1) * 32;
            if (A_F16) {
                cpa16(nstg + sdst0, Ahp0 + ko * 2, sz0);
                cpa16(nstg + sdst1, Ahp1 + ko * 2, sz1);
                CP_COMMIT();
            } else {
                a00 = aok0 ? *(const float4*)(Afp0 + ko) : z4;
                a01 = aok0 ? *(const float4*)(Afp0 + ko + 4) : z4;
                a10 = aok1 ? *(const float4*)(Afp1 + ko) : z4;
                a11 = aok1 ? *(const float4*)(Afp1 + ko + 4) : z4;
            }
            b00 = *(const float4*)(Bfp0 + ko);
            b01 = *(const float4*)(Bfp0 + ko + 4);
            b10 = *(const float4*)(Bfp1 + ko);
            b11 = *(const float4*)(Bfp1 + ko + 4);
        }
#pragma unroll
        for (int k16 = 0; k16 < 2; ++k16) {
            const uint32_t kb = k16 * 32;
            uint32_t ah[2][4], bh[4][4];
            ldsm4(ah[0], stg + a_off + kb);
            ldsm4(ah[1], stg + a_off + kb + 16 * SROW);
#pragma unroll
            for (int bj = 0; bj < 4; ++bj)
                ldsm4(bh[bj], stg + OFF_BHI + b_off + kb + bj * 16 * SROW);
#pragma unroll
            for (int mi = 0; mi < 2; ++mi)
#pragma unroll
                for (int nj = 0; nj < 8; ++nj)
                    mma16816(acc[mi][nj], ah[mi], &bh[nj >> 1][(nj & 1) * 2]);
        }
        if (more) {
            if (!A_F16) {
                round_sts(nstg + sdst0, a00, a01);
                round_sts(nstg + sdst1, a10, a11);
            }
            round_sts(nstg + OFF_BHI + sdst0, b00, b01);
            round_sts(nstg + OFF_BHI + sdst1, b10, b11);
            if (A_F16) CP_WAIT0();
        }
        __syncthreads();
    }

    // ------------------------------ epilogue --------------------------------
    const float* bs = (const float*)(smem + BIAS_OFF);
    uint32_t* yh32 = (uint32_t*)g_yh;
#pragma unroll
    for (int mi = 0; mi < 2; ++mi) {
        const int r = warp_m * 32 + mi * 16 + (lane >> 2);
#pragma unroll
        for (int nj = 0; nj < 8; ++nj) {
            const int c = warp_n * 64 + nj * 8 + (lane & 3) * 2;
            float2 v0 = make_float2(acc[mi][nj][0], acc[mi][nj][1]);
            float2 v1 = make_float2(acc[mi][nj][2], acc[mi][nj][3]);
            if (ADD_BIAS) {
                const float b0 = bs[c], b1 = bs[c + 1];
                v0.x += b0; v0.y += b1;
                v1.x += b0; v1.y += b1;
            }
            if (F16_OUT) {
                if (r < mrows) {
                    const size_t ix = ((size_t)(row0 + r) * N + n0 + c) >> 1;
                    yh32[ix] = h2rn(v0.x, v0.y);
                }
                if (r + 8 < mrows) {
                    const size_t ix = ((size_t)(row0 + r + 8) * N + n0 + c) >> 1;
                    yh32[ix] = h2rn(v1.x, v1.y);
                }
            } else {
                if (r < mrows)
                    *(float2*)&Cf[(size_t)(row0 + r) * N + n0 + c] = v0;
                if (r + 8 < mrows)
                    *(float2*)&Cf[(size_t)(row0 + r + 8) * N + n0 + c] = v1;
            }
        }
    }
}

// ------------------------------- launch -------------------------------------
extern "C" void kernel_launch(void* const* d_in, const int* in_sizes, int n_in,
                              void* d_out, int out_size) {
    const float* inp  = (const float*)d_in[0];
    const int*   cnt  = (const int*)  d_in[1];
    const float* wgt  = (const float*)d_in[2];
    const float* bias = (const float*)d_in[3];
    const float* comp = (const float*)d_in[4];
    float* out = (float*)d_out;

    const int E     = in_sizes[1];
    const int D_out = in_sizes[3] / E;
    const int D_in  = in_sizes[2] / in_sizes[3];
    const int T     = in_sizes[0] / D_in;
    const int S     = in_sizes[4] / in_sizes[3];
    const int maxtiles = T / BM + E;

    cudaFuncSetAttribute(moe_hmma<true, false, true>,
                         cudaFuncAttributeMaxDynamicSharedMemorySize, SMEM_TOTAL);
    cudaFuncSetAttribute(moe_hmma<false, true, false>,
                         cudaFuncAttributeMaxDynamicSharedMemorySize, SMEM_TOTAL);

    __half* yh;
    cudaGetSymbolAddress((void**)&yh, g_yh);

    setup_kernel<<<1, 1>>>(cnt, E);

    // GEMM1: y = x @ W^T + b  (x/W rounded in-loop; y emitted fp16)
    moe_hmma<true, false, true><<<dim3(D_out / BN, maxtiles), NTH, SMEM_TOTAL>>>(
        inp, nullptr, wgt, bias, nullptr, D_in, D_out);
    // GEMM2: out = y @ C^T  (y fp16 via cp.async; comp rounded in-loop)
    moe_hmma<false, true, false><<<dim3(S / BN, maxtiles), NTH, SMEM_TOTAL>>>(
        nullptr, yh, comp, nullptr, out, D_out, S);
}